// round 1
// baseline (speedup 1.0000x reference)
#include <cuda_runtime.h>
#include <math.h>

// ---------------- problem constants ----------------
#define Bb   4
#define Vv   4096
#define Kk   128
#define Cc   128
#define NBLK 4

// ---------------- scratch (device globals; no allocs) ----------------
__device__ float g_x[Bb*Vv*Cc];       // running features
__device__ float g_xdiff[Bb*Vv*Cc];
__device__ float g_gx[Bb*Vv*Cc];
__device__ float g_gy[Bb*Vv*Cc];
__device__ float g_br[Bb*Vv*Cc];
__device__ float g_gfeat[Bb*Vv*Cc];
__device__ float g_h0[Bb*Vv*Cc];
__device__ float g_h1[Bb*Vv*Cc];
__device__ float g_xspec[Bb*Kk*Cc];
__device__ float g_yspec[Bb*Kk*Cc];

// ---------------- tiled GEMM core: C[M,128] = A[M,K] @ B[K,128] ----------------
// BM=64, BN=128, BK=16, 256 threads, each thread computes 4x8 outputs.
#define BM 64
#define BN 128
#define BK 16
#define AS_LD 68   // padded, 16B-aligned stride
#define BS_LD 132

struct Smem {
    float As[BK][AS_LD];
    float Bs[BK][BS_LD];
};

__device__ __forceinline__ void gemm_tile(
    const float* __restrict__ A, int lda,
    const float* __restrict__ B,        // K x 128, row stride 128
    int K, int row0, float acc[4][8], Smem& s)
{
    const int tid   = threadIdx.x;
    const int arow  = tid >> 2;          // 0..63
    const int acol4 = (tid & 3) << 2;    // 0,4,8,12
    const int brow  = tid >> 4;          // 0..15
    const int bcol  = (tid & 15) << 3;   // 0..120 step 8
    const int ty    = tid >> 4;
    const int tx    = tid & 15;

    for (int kt = 0; kt < K; kt += BK) {
        float4 a = *(const float4*)(A + (long)(row0 + arow) * lda + kt + acol4);
        s.As[acol4 + 0][arow] = a.x;
        s.As[acol4 + 1][arow] = a.y;
        s.As[acol4 + 2][arow] = a.z;
        s.As[acol4 + 3][arow] = a.w;
        float4 b0 = *(const float4*)(B + (long)(kt + brow) * BN + bcol);
        float4 b1 = *(const float4*)(B + (long)(kt + brow) * BN + bcol + 4);
        *(float4*)&s.Bs[brow][bcol]     = b0;
        *(float4*)&s.Bs[brow][bcol + 4] = b1;
        __syncthreads();
        #pragma unroll
        for (int k = 0; k < BK; k++) {
            float4 av  = *(const float4*)&s.As[k][ty * 4];
            float4 bva = *(const float4*)&s.Bs[k][tx * 4];
            float4 bvb = *(const float4*)&s.Bs[k][64 + tx * 4];
            float am[4] = {av.x, av.y, av.z, av.w};
            float bn[8] = {bva.x, bva.y, bva.z, bva.w, bvb.x, bvb.y, bvb.z, bvb.w};
            #pragma unroll
            for (int i = 0; i < 4; i++)
                #pragma unroll
                for (int j = 0; j < 8; j++)
                    acc[i][j] += am[i] * bn[j];
        }
        __syncthreads();
    }
}

__device__ __forceinline__ void zero_acc(float acc[4][8]) {
    #pragma unroll
    for (int i = 0; i < 4; i++)
        #pragma unroll
        for (int j = 0; j < 8; j++) acc[i][j] = 0.0f;
}

// store tile: col mapping j<4 -> tx*4+j ; j>=4 -> 64+tx*4+(j-4)
__device__ __forceinline__ void store_tile(float* __restrict__ C, int row0, float acc[4][8]) {
    const int ty = threadIdx.x >> 4;
    const int tx = threadIdx.x & 15;
    #pragma unroll
    for (int i = 0; i < 4; i++) {
        int r = row0 + ty * 4 + i;
        float4 o0 = make_float4(acc[i][0], acc[i][1], acc[i][2], acc[i][3]);
        float4 o1 = make_float4(acc[i][4], acc[i][5], acc[i][6], acc[i][7]);
        *(float4*)(C + (long)r * 128 + tx * 4)      = o0;
        *(float4*)(C + (long)r * 128 + 64 + tx * 4) = o1;
    }
}

// ---------------- kernels ----------------

// x = x_in @ Wf + bf   (16384 x 128, K=16)
__global__ __launch_bounds__(256) void k_input(const float* __restrict__ xin,
                                               const float* __restrict__ Wf,
                                               const float* __restrict__ bf) {
    int gid = blockIdx.x * 256 + threadIdx.x;
    int r = gid >> 7, c = gid & 127;
    float s = bf[c];
    #pragma unroll
    for (int k = 0; k < 16; k++) s += xin[r * 16 + k] * Wf[k * 128 + c];
    g_x[gid] = s;
}

__global__ __launch_bounds__(256) void k_zero_spec() {
    int gid = blockIdx.x * 256 + threadIdx.x;
    g_xspec[gid] = 0.0f;
}

// x_spec[b] += evecs[b]^T @ (x[b] * mass[b]) ; split over V with atomics
__global__ __launch_bounds__(256) void k_spec(const float* __restrict__ evecs,
                                              const float* __restrict__ mass) {
    __shared__ float Ev[16][132];
    __shared__ float Xs[16][132];
    int b  = blockIdx.y;
    int v0 = blockIdx.x * 128;
    int tid = threadIdx.x;
    int r   = tid >> 4;          // 0..15 (v offset within chunk)
    int col = (tid & 15) << 3;   // 0..120
    int ty  = tid >> 4, tx = tid & 15;

    float acc[8][8];
    #pragma unroll
    for (int i = 0; i < 8; i++)
        #pragma unroll
        for (int j = 0; j < 8; j++) acc[i][j] = 0.0f;

    for (int vc = 0; vc < 128; vc += 16) {
        int v = v0 + vc + r;
        const float* ep = evecs + (long)(b * Vv + v) * Kk + col;
        float4 e0 = *(const float4*)ep;
        float4 e1 = *(const float4*)(ep + 4);
        *(float4*)&Ev[r][col]     = e0;
        *(float4*)&Ev[r][col + 4] = e1;
        float m = mass[b * Vv + v];
        const float* xp = g_x + (long)(b * Vv + v) * Cc + col;
        float4 x0 = *(const float4*)xp;
        float4 x1 = *(const float4*)(xp + 4);
        x0.x *= m; x0.y *= m; x0.z *= m; x0.w *= m;
        x1.x *= m; x1.y *= m; x1.z *= m; x1.w *= m;
        *(float4*)&Xs[r][col]     = x0;
        *(float4*)&Xs[r][col + 4] = x1;
        __syncthreads();
        #pragma unroll
        for (int vv = 0; vv < 16; vv++) {
            float a[8], bb[8];
            *(float4*)&a[0]  = *(const float4*)&Ev[vv][ty * 4];
            *(float4*)&a[4]  = *(const float4*)&Ev[vv][64 + ty * 4];
            *(float4*)&bb[0] = *(const float4*)&Xs[vv][tx * 4];
            *(float4*)&bb[4] = *(const float4*)&Xs[vv][64 + tx * 4];
            #pragma unroll
            for (int i = 0; i < 8; i++)
                #pragma unroll
                for (int j = 0; j < 8; j++)
                    acc[i][j] += a[i] * bb[j];
        }
        __syncthreads();
    }
    float* outb = g_xspec + b * Kk * Cc;
    #pragma unroll
    for (int i = 0; i < 8; i++) {
        int kk = (i < 4) ? (ty * 4 + i) : (60 + ty * 4 + i);
        #pragma unroll
        for (int j = 0; j < 8; j++) {
            int cc = (j < 4) ? (tx * 4 + j) : (60 + tx * 4 + j);
            atomicAdd(&outb[kk * Cc + cc], acc[i][j]);
        }
    }
}

// y_spec = exp(-evals[b,k] * max(t[blk,c],1e-8)) * x_spec
__global__ __launch_bounds__(256) void k_scale(const float* __restrict__ evals,
                                               const float* __restrict__ t, int blk) {
    int gid = blockIdx.x * 256 + threadIdx.x;      // 65536 total
    int b = gid >> 14;
    int k = (gid >> 7) & 127;
    int c = gid & 127;
    float ti = fmaxf(t[blk * 128 + c], 1e-8f);
    g_yspec[gid] = expf(-evals[b * 128 + k] * ti) * g_xspec[gid];
}

// x_diff[b] = evecs[b] @ y_spec[b]
__global__ __launch_bounds__(256) void k_from_basis(const float* __restrict__ evecs) {
    __shared__ Smem s;
    int b = blockIdx.y;
    int row0 = blockIdx.x * BM;
    float acc[4][8]; zero_acc(acc);
    gemm_tile(evecs + (long)b * Vv * Kk, Kk, g_yspec + b * Kk * Cc, Kk, row0, acc, s);
    store_tile(g_xdiff + (long)b * Vv * Cc, row0, acc);
}

// gx/gy[b] = grad{X,Y}[b] @ x_diff[b]   (the big K=4096 GEMM)
__global__ __launch_bounds__(256) void k_grad(const float* __restrict__ gradX,
                                              const float* __restrict__ gradY) {
    __shared__ Smem s;
    int b = blockIdx.y, z = blockIdx.z;
    const float* A = (z ? gradY : gradX) + (long)b * Vv * Vv;
    float* O = (z ? g_gy : g_gx) + (long)b * Vv * Cc;
    int row0 = blockIdx.x * BM;
    float acc[4][8]; zero_acc(acc);
    gemm_tile(A, Vv, g_xdiff + (long)b * Vv * Cc, Vv, row0, acc, s);
    store_tile(O, row0, acc);
}

// br = gx @ Are - gy @ Aim
__global__ __launch_bounds__(256) void k_br(const float* __restrict__ Are,
                                            const float* __restrict__ Aim) {
    __shared__ Smem s;
    int b = blockIdx.y;
    long off = (long)b * Vv * Cc;
    int row0 = blockIdx.x * BM;
    float acc1[4][8]; zero_acc(acc1);
    gemm_tile(g_gx + off, Cc, Are, Cc, row0, acc1, s);
    float acc2[4][8]; zero_acc(acc2);
    gemm_tile(g_gy + off, Cc, Aim, Cc, row0, acc2, s);
    #pragma unroll
    for (int i = 0; i < 4; i++)
        #pragma unroll
        for (int j = 0; j < 8; j++) acc1[i][j] -= acc2[i][j];
    store_tile(g_br + off, row0, acc1);
}

// bi = gy @ Are + gx @ Aim ; gfeat = tanh(gx*br + gy*bi)
__global__ __launch_bounds__(256) void k_gfeat(const float* __restrict__ Are,
                                               const float* __restrict__ Aim) {
    __shared__ Smem s;
    int b = blockIdx.y;
    long off = (long)b * Vv * Cc;
    int row0 = blockIdx.x * BM;
    float acc1[4][8]; zero_acc(acc1);
    gemm_tile(g_gy + off, Cc, Are, Cc, row0, acc1, s);
    float acc2[4][8]; zero_acc(acc2);
    gemm_tile(g_gx + off, Cc, Aim, Cc, row0, acc2, s);
    const int ty = threadIdx.x >> 4, tx = threadIdx.x & 15;
    #pragma unroll
    for (int i = 0; i < 4; i++) {
        int r = row0 + ty * 4 + i;
        long base0 = off + (long)r * 128 + tx * 4;
        long base1 = base0 + 64;
        float4 gx0 = *(const float4*)(g_gx + base0);
        float4 gx1 = *(const float4*)(g_gx + base1);
        float4 gy0 = *(const float4*)(g_gy + base0);
        float4 gy1 = *(const float4*)(g_gy + base1);
        float4 br0 = *(const float4*)(g_br + base0);
        float4 br1 = *(const float4*)(g_br + base1);
        float bi[8];
        #pragma unroll
        for (int j = 0; j < 8; j++) bi[j] = acc1[i][j] + acc2[i][j];
        float4 o0, o1;
        o0.x = tanhf(gx0.x * br0.x + gy0.x * bi[0]);
        o0.y = tanhf(gx0.y * br0.y + gy0.y * bi[1]);
        o0.z = tanhf(gx0.z * br0.z + gy0.z * bi[2]);
        o0.w = tanhf(gx0.w * br0.w + gy0.w * bi[3]);
        o1.x = tanhf(gx1.x * br1.x + gy1.x * bi[4]);
        o1.y = tanhf(gx1.y * br1.y + gy1.y * bi[5]);
        o1.z = tanhf(gx1.z * br1.z + gy1.z * bi[6]);
        o1.w = tanhf(gx1.w * br1.w + gy1.w * bi[7]);
        *(float4*)(g_gfeat + base0) = o0;
        *(float4*)(g_gfeat + base1) = o1;
    }
}

// h0 = relu([x | x_diff | gfeat] @ W0 + b0)   M=16384, K=384 in 3 segments
__global__ __launch_bounds__(256) void k_mlp0(const float* __restrict__ W0,
                                              const float* __restrict__ b0) {
    __shared__ Smem s;
    int row0 = blockIdx.x * BM;   // global rows 0..16383
    float acc[4][8]; zero_acc(acc);
    gemm_tile(g_x,     Cc, W0,             Cc, row0, acc, s);
    gemm_tile(g_xdiff, Cc, W0 + 128 * 128, Cc, row0, acc, s);
    gemm_tile(g_gfeat, Cc, W0 + 256 * 128, Cc, row0, acc, s);
    const int ty = threadIdx.x >> 4, tx = threadIdx.x & 15;
    float4 bb0 = *(const float4*)(b0 + tx * 4);
    float4 bb1 = *(const float4*)(b0 + 64 + tx * 4);
    float bv[8] = {bb0.x, bb0.y, bb0.z, bb0.w, bb1.x, bb1.y, bb1.z, bb1.w};
    #pragma unroll
    for (int i = 0; i < 4; i++)
        #pragma unroll
        for (int j = 0; j < 8; j++) acc[i][j] = fmaxf(acc[i][j] + bv[j], 0.0f);
    store_tile(g_h0, row0, acc);
}

// h1 = relu(h0 @ W1 + b1)
__global__ __launch_bounds__(256) void k_mlp1(const float* __restrict__ W1,
                                              const float* __restrict__ b1) {
    __shared__ Smem s;
    int row0 = blockIdx.x * BM;
    float acc[4][8]; zero_acc(acc);
    gemm_tile(g_h0, Cc, W1, Cc, row0, acc, s);
    const int tx = threadIdx.x & 15;
    float4 bb0 = *(const float4*)(b1 + tx * 4);
    float4 bb1 = *(const float4*)(b1 + 64 + tx * 4);
    float bv[8] = {bb0.x, bb0.y, bb0.z, bb0.w, bb1.x, bb1.y, bb1.z, bb1.w};
    #pragma unroll
    for (int i = 0; i < 4; i++)
        #pragma unroll
        for (int j = 0; j < 8; j++) acc[i][j] = fmaxf(acc[i][j] + bv[j], 0.0f);
    store_tile(g_h1, row0, acc);
}

// x += h1 @ W2 + b2   (residual)
__global__ __launch_bounds__(256) void k_mlp2(const float* __restrict__ W2,
                                              const float* __restrict__ b2) {
    __shared__ Smem s;
    int row0 = blockIdx.x * BM;
    float acc[4][8]; zero_acc(acc);
    gemm_tile(g_h1, Cc, W2, Cc, row0, acc, s);
    const int ty = threadIdx.x >> 4, tx = threadIdx.x & 15;
    float4 bb0 = *(const float4*)(b2 + tx * 4);
    float4 bb1 = *(const float4*)(b2 + 64 + tx * 4);
    float bv[8] = {bb0.x, bb0.y, bb0.z, bb0.w, bb1.x, bb1.y, bb1.z, bb1.w};
    #pragma unroll
    for (int i = 0; i < 4; i++) {
        int r = row0 + ty * 4 + i;
        long base0 = (long)r * 128 + tx * 4;
        long base1 = base0 + 64;
        float4 x0 = *(const float4*)(g_x + base0);
        float4 x1 = *(const float4*)(g_x + base1);
        x0.x += acc[i][0] + bv[0]; x0.y += acc[i][1] + bv[1];
        x0.z += acc[i][2] + bv[2]; x0.w += acc[i][3] + bv[3];
        x1.x += acc[i][4] + bv[4]; x1.y += acc[i][5] + bv[5];
        x1.z += acc[i][6] + bv[6]; x1.w += acc[i][7] + bv[7];
        *(float4*)(g_x + base0) = x0;
        *(float4*)(g_x + base1) = x1;
    }
}

// out = x @ Wl + bl
__global__ __launch_bounds__(256) void k_final(const float* __restrict__ Wl,
                                               const float* __restrict__ bl,
                                               float* __restrict__ out) {
    __shared__ Smem s;
    int row0 = blockIdx.x * BM;
    float acc[4][8]; zero_acc(acc);
    gemm_tile(g_x, Cc, Wl, Cc, row0, acc, s);
    const int tx = threadIdx.x & 15;
    float4 bb0 = *(const float4*)(bl + tx * 4);
    float4 bb1 = *(const float4*)(bl + 64 + tx * 4);
    float bv[8] = {bb0.x, bb0.y, bb0.z, bb0.w, bb1.x, bb1.y, bb1.z, bb1.w};
    #pragma unroll
    for (int i = 0; i < 4; i++)
        #pragma unroll
        for (int j = 0; j < 8; j++) acc[i][j] += bv[j];
    store_tile(out, row0, acc);
}

// ---------------- launch ----------------
extern "C" void kernel_launch(void* const* d_in, const int* in_sizes, int n_in,
                              void* d_out, int out_size) {
    const float* x_in  = (const float*)d_in[0];
    const float* mass  = (const float*)d_in[1];
    const float* evals = (const float*)d_in[2];
    const float* evecs = (const float*)d_in[3];
    const float* gradX = (const float*)d_in[4];
    const float* gradY = (const float*)d_in[5];
    const float* Wf    = (const float*)d_in[6];
    const float* bf    = (const float*)d_in[7];
    const float* Wl    = (const float*)d_in[8];
    const float* bl    = (const float*)d_in[9];
    const float* t     = (const float*)d_in[10];
    const float* Are   = (const float*)d_in[11];
    const float* Aim   = (const float*)d_in[12];
    const float* W0    = (const float*)d_in[13];
    const float* b0    = (const float*)d_in[14];
    const float* W1    = (const float*)d_in[15];
    const float* b1    = (const float*)d_in[16];
    const float* W2    = (const float*)d_in[17];
    const float* b2    = (const float*)d_in[18];
    float* out = (float*)d_out;

    k_input<<<(Bb * Vv * Cc) / 256, 256>>>(x_in, Wf, bf);

    for (int i = 0; i < NBLK; i++) {
        k_zero_spec<<<(Bb * Kk * Cc) / 256, 256>>>();
        k_spec<<<dim3(Vv / 128, Bb), 256>>>(evecs, mass);
        k_scale<<<(Bb * Kk * Cc) / 256, 256>>>(evals, t, i);
        k_from_basis<<<dim3(Vv / BM, Bb), 256>>>(evecs);
        k_grad<<<dim3(Vv / BM, Bb, 2), 256>>>(gradX, gradY);
        k_br<<<dim3(Vv / BM, Bb), 256>>>(Are + i * Cc * Cc, Aim + i * Cc * Cc);
        k_gfeat<<<dim3(Vv / BM, Bb), 256>>>(Are + i * Cc * Cc, Aim + i * Cc * Cc);
        k_mlp0<<<(Bb * Vv) / BM, 256>>>(W0 + i * 3 * Cc * Cc, b0 + i * Cc);
        k_mlp1<<<(Bb * Vv) / BM, 256>>>(W1 + i * Cc * Cc, b1 + i * Cc);
        k_mlp2<<<(Bb * Vv) / BM, 256>>>(W2 + i * Cc * Cc, b2 + i * Cc);
    }

    k_final<<<(Bb * Vv) / BM, 256>>>(Wl, bl, out);
}

// round 2
// speedup vs baseline: 2.5209x; 2.5209x over previous
#include <cuda_runtime.h>
#include <math.h>

// ---------------- problem constants ----------------
#define Bb   4
#define Vv   4096
#define Kk   128
#define Cc   128
#define NBLK 4

// ---------------- scratch (device globals; no allocs) ----------------
__device__ float g_x[Bb*Vv*Cc];       // running features
__device__ float g_xdiff[Bb*Vv*Cc];
__device__ float g_gx[Bb*Vv*Cc];
__device__ float g_gy[Bb*Vv*Cc];
__device__ float g_br[Bb*Vv*Cc];
__device__ float g_gfeat[Bb*Vv*Cc];
__device__ float g_h0[Bb*Vv*Cc];
__device__ float g_h1[Bb*Vv*Cc];
__device__ float g_gxe[Bb*Vv*Kk];     // gradX @ evecs (precomputed once)
__device__ float g_gye[Bb*Vv*Kk];     // gradY @ evecs
__device__ float g_xspec[Bb*Kk*Cc];
__device__ float g_yspec[Bb*Kk*Cc];

// ---------------- tiled GEMM core: C[M,128] = A[M,K] @ B[K,128] ----------------
// BM=64, BN=128, BK=16, 256 threads, each thread computes 4x8 outputs.
#define BM 64
#define BN 128
#define BK 16
#define AS_LD 68   // padded, 16B-aligned stride
#define BS_LD 132

struct Smem {
    float As[BK][AS_LD];
    float Bs[BK][BS_LD];
};

__device__ __forceinline__ void gemm_tile(
    const float* __restrict__ A, int lda,
    const float* __restrict__ B,        // K x 128, row stride 128
    int K, int row0, float acc[4][8], Smem& s)
{
    const int tid   = threadIdx.x;
    const int arow  = tid >> 2;          // 0..63
    const int acol4 = (tid & 3) << 2;    // 0,4,8,12
    const int brow  = tid >> 4;          // 0..15
    const int bcol  = (tid & 15) << 3;   // 0..120 step 8
    const int ty    = tid >> 4;
    const int tx    = tid & 15;

    for (int kt = 0; kt < K; kt += BK) {
        float4 a = *(const float4*)(A + (long)(row0 + arow) * lda + kt + acol4);
        s.As[acol4 + 0][arow] = a.x;
        s.As[acol4 + 1][arow] = a.y;
        s.As[acol4 + 2][arow] = a.z;
        s.As[acol4 + 3][arow] = a.w;
        float4 b0 = *(const float4*)(B + (long)(kt + brow) * BN + bcol);
        float4 b1 = *(const float4*)(B + (long)(kt + brow) * BN + bcol + 4);
        *(float4*)&s.Bs[brow][bcol]     = b0;
        *(float4*)&s.Bs[brow][bcol + 4] = b1;
        __syncthreads();
        #pragma unroll
        for (int k = 0; k < BK; k++) {
            float4 av  = *(const float4*)&s.As[k][ty * 4];
            float4 bva = *(const float4*)&s.Bs[k][tx * 4];
            float4 bvb = *(const float4*)&s.Bs[k][64 + tx * 4];
            float am[4] = {av.x, av.y, av.z, av.w};
            float bn[8] = {bva.x, bva.y, bva.z, bva.w, bvb.x, bvb.y, bvb.z, bvb.w};
            #pragma unroll
            for (int i = 0; i < 4; i++)
                #pragma unroll
                for (int j = 0; j < 8; j++)
                    acc[i][j] += am[i] * bn[j];
        }
        __syncthreads();
    }
}

__device__ __forceinline__ void zero_acc(float acc[4][8]) {
    #pragma unroll
    for (int i = 0; i < 4; i++)
        #pragma unroll
        for (int j = 0; j < 8; j++) acc[i][j] = 0.0f;
}

// store tile: col mapping j<4 -> tx*4+j ; j>=4 -> 64+tx*4+(j-4)
__device__ __forceinline__ void store_tile(float* __restrict__ C, int row0, float acc[4][8]) {
    const int ty = threadIdx.x >> 4;
    const int tx = threadIdx.x & 15;
    #pragma unroll
    for (int i = 0; i < 4; i++) {
        int r = row0 + ty * 4 + i;
        float4 o0 = make_float4(acc[i][0], acc[i][1], acc[i][2], acc[i][3]);
        float4 o1 = make_float4(acc[i][4], acc[i][5], acc[i][6], acc[i][7]);
        *(float4*)(C + (long)r * 128 + tx * 4)      = o0;
        *(float4*)(C + (long)r * 128 + 64 + tx * 4) = o1;
    }
}

// ---------------- kernels ----------------

// x = x_in @ Wf + bf   (16384 x 128, K=16)
__global__ __launch_bounds__(256) void k_input(const float* __restrict__ xin,
                                               const float* __restrict__ Wf,
                                               const float* __restrict__ bf) {
    int gid = blockIdx.x * 256 + threadIdx.x;
    int r = gid >> 7, c = gid & 127;
    float s = bf[c];
    #pragma unroll
    for (int k = 0; k < 16; k++) s += xin[r * 16 + k] * Wf[k * 128 + c];
    g_x[gid] = s;
}

// Precompute (once): GXE[b] = gradX[b] @ evecs[b], GYE[b] = gradY[b] @ evecs[b]
// A: [V,V] lda=Vv ; B: evecs [V rows x 128 cols] stride 128 ; K=Vv
__global__ __launch_bounds__(256) void k_grad_evecs(const float* __restrict__ gradX,
                                                    const float* __restrict__ gradY,
                                                    const float* __restrict__ evecs) {
    __shared__ Smem s;
    int b = blockIdx.y, z = blockIdx.z;
    const float* A = (z ? gradY : gradX) + (long)b * Vv * Vv;
    float* O = (z ? g_gye : g_gxe) + (long)b * Vv * Kk;
    int row0 = blockIdx.x * BM;
    float acc[4][8]; zero_acc(acc);
    gemm_tile(A, Vv, evecs + (long)b * Vv * Kk, Vv, row0, acc, s);
    store_tile(O, row0, acc);
}

__global__ __launch_bounds__(256) void k_zero_spec() {
    int gid = blockIdx.x * 256 + threadIdx.x;
    g_xspec[gid] = 0.0f;
}

// x_spec[b] += evecs[b]^T @ (x[b] * mass[b]) ; split over V with atomics
__global__ __launch_bounds__(256) void k_spec(const float* __restrict__ evecs,
                                              const float* __restrict__ mass) {
    __shared__ float Ev[16][132];
    __shared__ float Xs[16][132];
    int b  = blockIdx.y;
    int v0 = blockIdx.x * 128;
    int tid = threadIdx.x;
    int r   = tid >> 4;          // 0..15 (v offset within chunk)
    int col = (tid & 15) << 3;   // 0..120
    int ty  = tid >> 4, tx = tid & 15;

    float acc[8][8];
    #pragma unroll
    for (int i = 0; i < 8; i++)
        #pragma unroll
        for (int j = 0; j < 8; j++) acc[i][j] = 0.0f;

    for (int vc = 0; vc < 128; vc += 16) {
        int v = v0 + vc + r;
        const float* ep = evecs + (long)(b * Vv + v) * Kk + col;
        float4 e0 = *(const float4*)ep;
        float4 e1 = *(const float4*)(ep + 4);
        *(float4*)&Ev[r][col]     = e0;
        *(float4*)&Ev[r][col + 4] = e1;
        float m = mass[b * Vv + v];
        const float* xp = g_x + (long)(b * Vv + v) * Cc + col;
        float4 x0 = *(const float4*)xp;
        float4 x1 = *(const float4*)(xp + 4);
        x0.x *= m; x0.y *= m; x0.z *= m; x0.w *= m;
        x1.x *= m; x1.y *= m; x1.z *= m; x1.w *= m;
        *(float4*)&Xs[r][col]     = x0;
        *(float4*)&Xs[r][col + 4] = x1;
        __syncthreads();
        #pragma unroll
        for (int vv = 0; vv < 16; vv++) {
            float a[8], bb[8];
            *(float4*)&a[0]  = *(const float4*)&Ev[vv][ty * 4];
            *(float4*)&a[4]  = *(const float4*)&Ev[vv][64 + ty * 4];
            *(float4*)&bb[0] = *(const float4*)&Xs[vv][tx * 4];
            *(float4*)&bb[4] = *(const float4*)&Xs[vv][64 + tx * 4];
            #pragma unroll
            for (int i = 0; i < 8; i++)
                #pragma unroll
                for (int j = 0; j < 8; j++)
                    acc[i][j] += a[i] * bb[j];
        }
        __syncthreads();
    }
    float* outb = g_xspec + b * Kk * Cc;
    #pragma unroll
    for (int i = 0; i < 8; i++) {
        int kk = (i < 4) ? (ty * 4 + i) : (60 + ty * 4 + i);
        #pragma unroll
        for (int j = 0; j < 8; j++) {
            int cc = (j < 4) ? (tx * 4 + j) : (60 + tx * 4 + j);
            atomicAdd(&outb[kk * Cc + cc], acc[i][j]);
        }
    }
}

// y_spec = exp(-evals[b,k] * max(t[blk,c],1e-8)) * x_spec
__global__ __launch_bounds__(256) void k_scale(const float* __restrict__ evals,
                                               const float* __restrict__ t, int blk) {
    int gid = blockIdx.x * 256 + threadIdx.x;      // 65536 total
    int b = gid >> 14;
    int k = (gid >> 7) & 127;
    int c = gid & 127;
    float ti = fmaxf(t[blk * 128 + c], 1e-8f);
    g_yspec[gid] = expf(-evals[b * 128 + k] * ti) * g_xspec[gid];
}

// z=0: x_diff = evecs @ y_spec ; z=1: gx = GXE @ y_spec ; z=2: gy = GYE @ y_spec
__global__ __launch_bounds__(256) void k_fbg(const float* __restrict__ evecs) {
    __shared__ Smem s;
    int b = blockIdx.y, z = blockIdx.z;
    const float* A;
    float* O;
    if (z == 0)      { A = evecs + (long)b * Vv * Kk; O = g_xdiff + (long)b * Vv * Cc; }
    else if (z == 1) { A = g_gxe + (long)b * Vv * Kk; O = g_gx + (long)b * Vv * Cc; }
    else             { A = g_gye + (long)b * Vv * Kk; O = g_gy + (long)b * Vv * Cc; }
    int row0 = blockIdx.x * BM;
    float acc[4][8]; zero_acc(acc);
    gemm_tile(A, Kk, g_yspec + b * Kk * Cc, Kk, row0, acc, s);
    store_tile(O, row0, acc);
}

// br = gx @ Are - gy @ Aim
__global__ __launch_bounds__(256) void k_br(const float* __restrict__ Are,
                                            const float* __restrict__ Aim) {
    __shared__ Smem s;
    int b = blockIdx.y;
    long off = (long)b * Vv * Cc;
    int row0 = blockIdx.x * BM;
    float acc1[4][8]; zero_acc(acc1);
    gemm_tile(g_gx + off, Cc, Are, Cc, row0, acc1, s);
    float acc2[4][8]; zero_acc(acc2);
    gemm_tile(g_gy + off, Cc, Aim, Cc, row0, acc2, s);
    #pragma unroll
    for (int i = 0; i < 4; i++)
        #pragma unroll
        for (int j = 0; j < 8; j++) acc1[i][j] -= acc2[i][j];
    store_tile(g_br + off, row0, acc1);
}

// bi = gy @ Are + gx @ Aim ; gfeat = tanh(gx*br + gy*bi)
__global__ __launch_bounds__(256) void k_gfeat(const float* __restrict__ Are,
                                               const float* __restrict__ Aim) {
    __shared__ Smem s;
    int b = blockIdx.y;
    long off = (long)b * Vv * Cc;
    int row0 = blockIdx.x * BM;
    float acc1[4][8]; zero_acc(acc1);
    gemm_tile(g_gy + off, Cc, Are, Cc, row0, acc1, s);
    float acc2[4][8]; zero_acc(acc2);
    gemm_tile(g_gx + off, Cc, Aim, Cc, row0, acc2, s);
    const int ty = threadIdx.x >> 4, tx = threadIdx.x & 15;
    #pragma unroll
    for (int i = 0; i < 4; i++) {
        int r = row0 + ty * 4 + i;
        long base0 = off + (long)r * 128 + tx * 4;
        long base1 = base0 + 64;
        float4 gx0 = *(const float4*)(g_gx + base0);
        float4 gx1 = *(const float4*)(g_gx + base1);
        float4 gy0 = *(const float4*)(g_gy + base0);
        float4 gy1 = *(const float4*)(g_gy + base1);
        float4 br0 = *(const float4*)(g_br + base0);
        float4 br1 = *(const float4*)(g_br + base1);
        float bi[8];
        #pragma unroll
        for (int j = 0; j < 8; j++) bi[j] = acc1[i][j] + acc2[i][j];
        float4 o0, o1;
        o0.x = tanhf(gx0.x * br0.x + gy0.x * bi[0]);
        o0.y = tanhf(gx0.y * br0.y + gy0.y * bi[1]);
        o0.z = tanhf(gx0.z * br0.z + gy0.z * bi[2]);
        o0.w = tanhf(gx0.w * br0.w + gy0.w * bi[3]);
        o1.x = tanhf(gx1.x * br1.x + gy1.x * bi[4]);
        o1.y = tanhf(gx1.y * br1.y + gy1.y * bi[5]);
        o1.z = tanhf(gx1.z * br1.z + gy1.z * bi[6]);
        o1.w = tanhf(gx1.w * br1.w + gy1.w * bi[7]);
        *(float4*)(g_gfeat + base0) = o0;
        *(float4*)(g_gfeat + base1) = o1;
    }
}

// h0 = relu([x | x_diff | gfeat] @ W0 + b0)   M=16384, K=384 in 3 segments
__global__ __launch_bounds__(256) void k_mlp0(const float* __restrict__ W0,
                                              const float* __restrict__ b0) {
    __shared__ Smem s;
    int row0 = blockIdx.x * BM;   // global rows 0..16383
    float acc[4][8]; zero_acc(acc);
    gemm_tile(g_x,     Cc, W0,             Cc, row0, acc, s);
    gemm_tile(g_xdiff, Cc, W0 + 128 * 128, Cc, row0, acc, s);
    gemm_tile(g_gfeat, Cc, W0 + 256 * 128, Cc, row0, acc, s);
    const int tx = threadIdx.x & 15;
    float4 bb0 = *(const float4*)(b0 + tx * 4);
    float4 bb1 = *(const float4*)(b0 + 64 + tx * 4);
    float bv[8] = {bb0.x, bb0.y, bb0.z, bb0.w, bb1.x, bb1.y, bb1.z, bb1.w};
    #pragma unroll
    for (int i = 0; i < 4; i++)
        #pragma unroll
        for (int j = 0; j < 8; j++) acc[i][j] = fmaxf(acc[i][j] + bv[j], 0.0f);
    store_tile(g_h0, row0, acc);
}

// h1 = relu(h0 @ W1 + b1)
__global__ __launch_bounds__(256) void k_mlp1(const float* __restrict__ W1,
                                              const float* __restrict__ b1) {
    __shared__ Smem s;
    int row0 = blockIdx.x * BM;
    float acc[4][8]; zero_acc(acc);
    gemm_tile(g_h0, Cc, W1, Cc, row0, acc, s);
    const int tx = threadIdx.x & 15;
    float4 bb0 = *(const float4*)(b1 + tx * 4);
    float4 bb1 = *(const float4*)(b1 + 64 + tx * 4);
    float bv[8] = {bb0.x, bb0.y, bb0.z, bb0.w, bb1.x, bb1.y, bb1.z, bb1.w};
    #pragma unroll
    for (int i = 0; i < 4; i++)
        #pragma unroll
        for (int j = 0; j < 8; j++) acc[i][j] = fmaxf(acc[i][j] + bv[j], 0.0f);
    store_tile(g_h1, row0, acc);
}

// x += h1 @ W2 + b2   (residual)
__global__ __launch_bounds__(256) void k_mlp2(const float* __restrict__ W2,
                                              const float* __restrict__ b2) {
    __shared__ Smem s;
    int row0 = blockIdx.x * BM;
    float acc[4][8]; zero_acc(acc);
    gemm_tile(g_h1, Cc, W2, Cc, row0, acc, s);
    const int ty = threadIdx.x >> 4, tx = threadIdx.x & 15;
    float4 bb0 = *(const float4*)(b2 + tx * 4);
    float4 bb1 = *(const float4*)(b2 + 64 + tx * 4);
    float bv[8] = {bb0.x, bb0.y, bb0.z, bb0.w, bb1.x, bb1.y, bb1.z, bb1.w};
    #pragma unroll
    for (int i = 0; i < 4; i++) {
        int r = row0 + ty * 4 + i;
        long base0 = (long)r * 128 + tx * 4;
        long base1 = base0 + 64;
        float4 x0 = *(const float4*)(g_x + base0);
        float4 x1 = *(const float4*)(g_x + base1);
        x0.x += acc[i][0] + bv[0]; x0.y += acc[i][1] + bv[1];
        x0.z += acc[i][2] + bv[2]; x0.w += acc[i][3] + bv[3];
        x1.x += acc[i][4] + bv[4]; x1.y += acc[i][5] + bv[5];
        x1.z += acc[i][6] + bv[6]; x1.w += acc[i][7] + bv[7];
        *(float4*)(g_x + base0) = x0;
        *(float4*)(g_x + base1) = x1;
    }
}

// out = x @ Wl + bl
__global__ __launch_bounds__(256) void k_final(const float* __restrict__ Wl,
                                               const float* __restrict__ bl,
                                               float* __restrict__ out) {
    __shared__ Smem s;
    int row0 = blockIdx.x * BM;
    float acc[4][8]; zero_acc(acc);
    gemm_tile(g_x, Cc, Wl, Cc, row0, acc, s);
    const int tx = threadIdx.x & 15;
    float4 bb0 = *(const float4*)(bl + tx * 4);
    float4 bb1 = *(const float4*)(bl + 64 + tx * 4);
    float bv[8] = {bb0.x, bb0.y, bb0.z, bb0.w, bb1.x, bb1.y, bb1.z, bb1.w};
    #pragma unroll
    for (int i = 0; i < 4; i++)
        #pragma unroll
        for (int j = 0; j < 8; j++) acc[i][j] += bv[j];
    store_tile(out, row0, acc);
}

// ---------------- launch ----------------
extern "C" void kernel_launch(void* const* d_in, const int* in_sizes, int n_in,
                              void* d_out, int out_size) {
    const float* x_in  = (const float*)d_in[0];
    const float* mass  = (const float*)d_in[1];
    const float* evals = (const float*)d_in[2];
    const float* evecs = (const float*)d_in[3];
    const float* gradX = (const float*)d_in[4];
    const float* gradY = (const float*)d_in[5];
    const float* Wf    = (const float*)d_in[6];
    const float* bf    = (const float*)d_in[7];
    const float* Wl    = (const float*)d_in[8];
    const float* bl    = (const float*)d_in[9];
    const float* t     = (const float*)d_in[10];
    const float* Are   = (const float*)d_in[11];
    const float* Aim   = (const float*)d_in[12];
    const float* W0    = (const float*)d_in[13];
    const float* b0    = (const float*)d_in[14];
    const float* W1    = (const float*)d_in[15];
    const float* b1    = (const float*)d_in[16];
    const float* W2    = (const float*)d_in[17];
    const float* b2    = (const float*)d_in[18];
    float* out = (float*)d_out;

    k_input<<<(Bb * Vv * Cc) / 256, 256>>>(x_in, Wf, bf);

    // one-time precompute: (gradX @ evecs), (gradY @ evecs)  — the only big GEMM
    k_grad_evecs<<<dim3(Vv / BM, Bb, 2), 256>>>(gradX, gradY, evecs);

    for (int i = 0; i < NBLK; i++) {
        k_zero_spec<<<(Bb * Kk * Cc) / 256, 256>>>();
        k_spec<<<dim3(Vv / 128, Bb), 256>>>(evecs, mass);
        k_scale<<<(Bb * Kk * Cc) / 256, 256>>>(evals, t, i);
        k_fbg<<<dim3(Vv / BM, Bb, 3), 256>>>(evecs);
        k_br<<<dim3(Vv / BM, Bb), 256>>>(Are + i * Cc * Cc, Aim + i * Cc * Cc);
        k_gfeat<<<dim3(Vv / BM, Bb), 256>>>(Are + i * Cc * Cc, Aim + i * Cc * Cc);
        k_mlp0<<<(Bb * Vv) / BM, 256>>>(W0 + i * 3 * Cc * Cc, b0 + i * Cc);
        k_mlp1<<<(Bb * Vv) / BM, 256>>>(W1 + i * Cc * Cc, b1 + i * Cc);
        k_mlp2<<<(Bb * Vv) / BM, 256>>>(W2 + i * Cc * Cc, b2 + i * Cc);
    }

    k_final<<<(Bb * Vv) / BM, 256>>>(Wl, bl, out);
}

// round 4
// speedup vs baseline: 4.7993x; 1.9038x over previous
#include <cuda_runtime.h>
#include <cuda_bf16.h>
#include <math.h>
#include <cstdint>

// ---------------- problem constants ----------------
#define Bb   4
#define Vv   4096
#define Kk   128
#define Cc   128
#define NBLK 4

// ---------------- scratch (device globals; no allocs) ----------------
__device__ float g_x[Bb*Vv*Cc];
__device__ float g_xdiff[Bb*Vv*Cc];
__device__ float g_gx[Bb*Vv*Cc];
__device__ float g_gy[Bb*Vv*Cc];
__device__ float g_br[Bb*Vv*Cc];
__device__ float g_gfeat[Bb*Vv*Cc];
__device__ float g_h0[Bb*Vv*Cc];
__device__ float g_h1[Bb*Vv*Cc];
__device__ float g_gxe[Bb*Vv*Kk];     // gradX @ evecs (precomputed once)
__device__ float g_gye[Bb*Vv*Kk];     // gradY @ evecs
__device__ float g_xspec[Bb*Kk*Cc];
__device__ float g_yspec[Bb*Kk*Cc];

// ---------------- bf16-split mma.sync GEMM core ----------------
// C[128,128] tile = A[128,K] @ B[K,128], 256 threads (8 warps), BK=32.
// A,B fp32 in gmem, converted to bf16 hi/lo during smem load.
// 3-term product: Ah*Bh + Ah*Bl + Al*Bh.

#define KP 20   // padded pair-stride (16 pairs + 4 pad)

struct MS {
    uint32_t Ah[128][KP];
    uint32_t Al[128][KP];
    uint32_t Bh[128][KP];
    uint32_t Bl[128][KP];
};

// pack two floats as bf16x2, e0 in low half
__device__ __forceinline__ uint32_t f2bf2(float e0, float e1) {
    uint32_t r;
    asm("cvt.rn.bf16x2.f32 %0, %1, %2;" : "=r"(r) : "f"(e1), "f"(e0));
    return r;
}
__device__ __forceinline__ float bhi(float v) {
    return __bfloat162float(__float2bfloat16(v));
}

#define MMA_BF16(c, a, b0, b1) \
    asm volatile("mma.sync.aligned.m16n8k16.row.col.f32.bf16.bf16.f32 " \
        "{%0,%1,%2,%3},{%4,%5,%6,%7},{%8,%9},{%0,%1,%2,%3};" \
        : "+f"((c)[0]), "+f"((c)[1]), "+f"((c)[2]), "+f"((c)[3]) \
        : "r"((a)[0]), "r"((a)[1]), "r"((a)[2]), "r"((a)[3]), "r"(b0), "r"(b1))

// A tile loader: 128 rows x 32 k (row-major, stride lda) -> As[m][kpair] hi/lo
__device__ __forceinline__ void ld_convA(MS& s, const float* __restrict__ A,
                                         long lda, int kt) {
    int row = threadIdx.x >> 1;
    int kh  = (threadIdx.x & 1) * 16;
    const float* ap = A + (long)row * lda + kt * 32 + kh;
    int p0 = kh >> 1;
    uint32_t h[8], l[8];
    #pragma unroll
    for (int q = 0; q < 4; q++) {
        float4 v = *(const float4*)(ap + q * 4);
        float h0 = bhi(v.x), h1 = bhi(v.y), h2 = bhi(v.z), h3 = bhi(v.w);
        h[q*2]   = f2bf2(h0, h1);
        h[q*2+1] = f2bf2(h2, h3);
        l[q*2]   = f2bf2(v.x - h0, v.y - h1);
        l[q*2+1] = f2bf2(v.z - h2, v.w - h3);
    }
    uint4* dh = (uint4*)&s.Ah[row][p0];
    dh[0] = make_uint4(h[0], h[1], h[2], h[3]);
    dh[1] = make_uint4(h[4], h[5], h[6], h[7]);
    uint4* dl = (uint4*)&s.Al[row][p0];
    dl[0] = make_uint4(l[0], l[1], l[2], l[3]);
    dl[1] = make_uint4(l[4], l[5], l[6], l[7]);
}

// B tile loader: B[K,128] row-major -> Bs[n][kpair] (transpose), sign applied
__device__ __forceinline__ void ld_convB(MS& s, const float* __restrict__ B,
                                         int kt, float sgn) {
    int n  = threadIdx.x & 127;
    int pr = threadIdx.x >> 7;   // 0/1
    #pragma unroll
    for (int i = 0; i < 8; i++) {
        int p = pr * 8 + i;
        float v0 = sgn * B[(long)(kt * 32 + 2 * p) * 128 + n];
        float v1 = sgn * B[(long)(kt * 32 + 2 * p + 1) * 128 + n];
        float h0 = bhi(v0), h1 = bhi(v1);
        s.Bh[n][p] = f2bf2(h0, h1);
        s.Bl[n][p] = f2bf2(v0 - h0, v1 - h1);
    }
}

__device__ __forceinline__ void mma_step(MS& s, int ks, float acc[2][8][4]) {
    int lane = threadIdx.x & 31, g = lane >> 2, t4 = lane & 3;
    int wid = threadIdx.x >> 5;
    int m0 = (wid & 3) * 32, n0 = (wid >> 2) * 64;
    int pb = ks * 8 + t4;
    uint32_t ah[2][4], al[2][4];
    #pragma unroll
    for (int mt = 0; mt < 2; mt++) {
        int m = m0 + mt * 16 + g;
        ah[mt][0] = s.Ah[m][pb];     ah[mt][1] = s.Ah[m+8][pb];
        ah[mt][2] = s.Ah[m][pb+4];   ah[mt][3] = s.Ah[m+8][pb+4];
        al[mt][0] = s.Al[m][pb];     al[mt][1] = s.Al[m+8][pb];
        al[mt][2] = s.Al[m][pb+4];   al[mt][3] = s.Al[m+8][pb+4];
    }
    #pragma unroll
    for (int nt = 0; nt < 8; nt++) {
        int n = n0 + nt * 8 + g;
        uint32_t bh0 = s.Bh[n][pb], bh1 = s.Bh[n][pb+4];
        uint32_t bl0 = s.Bl[n][pb], bl1 = s.Bl[n][pb+4];
        #pragma unroll
        for (int mt = 0; mt < 2; mt++) {
            MMA_BF16(acc[mt][nt], ah[mt], bh0, bh1);
            MMA_BF16(acc[mt][nt], ah[mt], bl0, bl1);
            MMA_BF16(acc[mt][nt], al[mt], bh0, bh1);
        }
    }
}

// accumulate: acc += A[128,K] @ (sgn*B[K,128]) ; A pre-offset to tile row0
__device__ __forceinline__ void mma_gemm(MS& s, const float* __restrict__ A,
                                         long lda, const float* __restrict__ B,
                                         int K, float sgn, float acc[2][8][4]) {
    for (int kt = 0; kt < K / 32; kt++) {
        __syncthreads();
        ld_convA(s, A, lda, kt);
        ld_convB(s, B, kt, sgn);
        __syncthreads();
        mma_step(s, 0, acc);
        mma_step(s, 1, acc);
    }
}

__device__ __forceinline__ void zacc(float acc[2][8][4]) {
    #pragma unroll
    for (int i = 0; i < 2; i++)
        #pragma unroll
        for (int j = 0; j < 8; j++)
            #pragma unroll
            for (int q = 0; q < 4; q++) acc[i][j][q] = 0.0f;
}

// ---------------- kernels ----------------

// x = x_in @ Wf + bf   (K=16, SIMT)
__global__ __launch_bounds__(256) void k_input(const float* __restrict__ xin,
                                               const float* __restrict__ Wf,
                                               const float* __restrict__ bf) {
    int gid = blockIdx.x * 256 + threadIdx.x;
    int r = gid >> 7, c = gid & 127;
    float s = bf[c];
    #pragma unroll
    for (int k = 0; k < 16; k++) s += xin[r * 16 + k] * Wf[k * 128 + c];
    g_x[gid] = s;
}

// precompute GXE/GYE = grad @ evecs ; grid (32, Bb, 2), K = 4096
__global__ __launch_bounds__(256) void k_bigmm(const float* __restrict__ gradX,
                                               const float* __restrict__ gradY,
                                               const float* __restrict__ evecs) {
    __shared__ MS s;
    int b = blockIdx.y, z = blockIdx.z;
    int row0 = blockIdx.x * 128;
    const float* A = (z ? gradY : gradX) + (long)b * Vv * Vv + (long)row0 * Vv;
    const float* B = evecs + (long)b * Vv * Kk;
    float* O = (z ? g_gye : g_gxe) + (long)b * Vv * Kk;
    float acc[2][8][4]; zacc(acc);
    mma_gemm(s, A, Vv, B, Vv, 1.0f, acc);
    int lane = threadIdx.x & 31, g = lane >> 4 ? 0 : 0;  // placeholder
    g = (lane >> 2); int t4 = lane & 3;
    int wid = threadIdx.x >> 5;
    int m0 = (wid & 3) * 32, n0 = (wid >> 2) * 64;
    #pragma unroll
    for (int mt = 0; mt < 2; mt++)
        #pragma unroll
        for (int nt = 0; nt < 8; nt++) {
            int r = row0 + m0 + mt * 16 + g;
            int c = n0 + nt * 8 + t4 * 2;
            *(float2*)(O + (long)r * 128 + c)       = make_float2(acc[mt][nt][0], acc[mt][nt][1]);
            *(float2*)(O + (long)(r + 8) * 128 + c) = make_float2(acc[mt][nt][2], acc[mt][nt][3]);
        }
}

__global__ __launch_bounds__(256) void k_zero_spec() {
    int gid = blockIdx.x * 256 + threadIdx.x;
    g_xspec[gid] = 0.0f;
}

// x_spec = evecs^T @ (x*mass), split-K over V with atomics. grid (32, Bb)
__global__ __launch_bounds__(256) void k_spec(const float* __restrict__ evecs,
                                              const float* __restrict__ mass) {
    __shared__ MS s;
    int b = blockIdx.y;
    int v0 = blockIdx.x * 128;
    float acc[2][8][4]; zacc(acc);
    int n  = threadIdx.x & 127;
    int pr = threadIdx.x >> 7;
    for (int kt = 0; kt < 4; kt++) {
        __syncthreads();
        // A: As[m=spec idx][k=v] = evecs[v][m]  (transpose load)
        #pragma unroll
        for (int i = 0; i < 8; i++) {
            int p = pr * 8 + i;
            long v = (long)(b * Vv + v0 + kt * 32 + 2 * p);
            float a0 = evecs[v * 128 + n];
            float a1 = evecs[(v + 1) * 128 + n];
            float h0 = bhi(a0), h1 = bhi(a1);
            s.Ah[n][p] = f2bf2(h0, h1);
            s.Al[n][p] = f2bf2(a0 - h0, a1 - h1);
        }
        // B: Bs[n=c][k=v] = x[v][c]*mass[v]  (transpose load)
        #pragma unroll
        for (int i = 0; i < 8; i++) {
            int p = pr * 8 + i;
            long v = (long)(b * Vv + v0 + kt * 32 + 2 * p);
            float m0f = mass[v], m1f = mass[v + 1];
            float v0f = g_x[v * 128 + n] * m0f;
            float v1f = g_x[(v + 1) * 128 + n] * m1f;
            float h0 = bhi(v0f), h1 = bhi(v1f);
            s.Bh[n][p] = f2bf2(h0, h1);
            s.Bl[n][p] = f2bf2(v0f - h0, v1f - h1);
        }
        __syncthreads();
        mma_step(s, 0, acc);
        mma_step(s, 1, acc);
    }
    int lane = threadIdx.x & 31, g = lane >> 2, t4 = lane & 3;
    int wid = threadIdx.x >> 5;
    int m0 = (wid & 3) * 32, n0 = (wid >> 2) * 64;
    float* outb = g_xspec + b * Kk * Cc;
    #pragma unroll
    for (int mt = 0; mt < 2; mt++)
        #pragma unroll
        for (int nt = 0; nt < 8; nt++) {
            int r = m0 + mt * 16 + g;
            int c = n0 + nt * 8 + t4 * 2;
            atomicAdd(&outb[r * 128 + c],       acc[mt][nt][0]);
            atomicAdd(&outb[r * 128 + c + 1],   acc[mt][nt][1]);
            atomicAdd(&outb[(r + 8) * 128 + c],     acc[mt][nt][2]);
            atomicAdd(&outb[(r + 8) * 128 + c + 1], acc[mt][nt][3]);
        }
}

// y_spec = exp(-evals*t) * x_spec
__global__ __launch_bounds__(256) void k_scale(const float* __restrict__ evals,
                                               const float* __restrict__ t, int blk) {
    int gid = blockIdx.x * 256 + threadIdx.x;
    int b = gid >> 14;
    int k = (gid >> 7) & 127;
    int c = gid & 127;
    float ti = fmaxf(t[blk * 128 + c], 1e-8f);
    g_yspec[gid] = expf(-evals[b * 128 + k] * ti) * g_xspec[gid];
}

// z=0: x_diff = evecs@y ; z=1: gx = GXE@y ; z=2: gy = GYE@y . grid (32, Bb, 3)
__global__ __launch_bounds__(256) void k_fbg(const float* __restrict__ evecs) {
    __shared__ MS s;
    int b = blockIdx.y, z = blockIdx.z;
    int row0 = blockIdx.x * 128;
    const float* A;
    float* O;
    if (z == 0)      { A = evecs + (long)b * Vv * Kk; O = g_xdiff + (long)b * Vv * Cc; }
    else if (z == 1) { A = g_gxe + (long)b * Vv * Kk; O = g_gx + (long)b * Vv * Cc; }
    else             { A = g_gye + (long)b * Vv * Kk; O = g_gy + (long)b * Vv * Cc; }
    float acc[2][8][4]; zacc(acc);
    mma_gemm(s, A + (long)row0 * Kk, Kk, g_yspec + b * Kk * Cc, Kk, 1.0f, acc);
    int lane = threadIdx.x & 31, g = lane >> 2, t4 = lane & 3;
    int wid = threadIdx.x >> 5;
    int m0 = (wid & 3) * 32, n0 = (wid >> 2) * 64;
    #pragma unroll
    for (int mt = 0; mt < 2; mt++)
        #pragma unroll
        for (int nt = 0; nt < 8; nt++) {
            int r = row0 + m0 + mt * 16 + g;
            int c = n0 + nt * 8 + t4 * 2;
            *(float2*)(O + (long)r * 128 + c)       = make_float2(acc[mt][nt][0], acc[mt][nt][1]);
            *(float2*)(O + (long)(r + 8) * 128 + c) = make_float2(acc[mt][nt][2], acc[mt][nt][3]);
        }
}

// br = gx@Are - gy@Aim . grid (32, Bb)
__global__ __launch_bounds__(256) void k_br(const float* __restrict__ Are,
                                            const float* __restrict__ Aim) {
    __shared__ MS s;
    int b = blockIdx.y;
    long off = (long)b * Vv * Cc;
    int row0 = blockIdx.x * 128;
    float acc[2][8][4]; zacc(acc);
    mma_gemm(s, g_gx + off + (long)row0 * Cc, Cc, Are, Cc, 1.0f, acc);
    mma_gemm(s, g_gy + off + (long)row0 * Cc, Cc, Aim, Cc, -1.0f, acc);
    int lane = threadIdx.x & 31, g = lane >> 2, t4 = lane & 3;
    int wid = threadIdx.x >> 5;
    int m0 = (wid & 3) * 32, n0 = (wid >> 2) * 64;
    #pragma unroll
    for (int mt = 0; mt < 2; mt++)
        #pragma unroll
        for (int nt = 0; nt < 8; nt++) {
            int r = row0 + m0 + mt * 16 + g;
            int c = n0 + nt * 8 + t4 * 2;
            *(float2*)(g_br + off + (long)r * 128 + c)       = make_float2(acc[mt][nt][0], acc[mt][nt][1]);
            *(float2*)(g_br + off + (long)(r + 8) * 128 + c) = make_float2(acc[mt][nt][2], acc[mt][nt][3]);
        }
}

// bi = gy@Are + gx@Aim ; gfeat = tanh(gx*br + gy*bi) . grid (32, Bb)
__global__ __launch_bounds__(256) void k_gfeat(const float* __restrict__ Are,
                                               const float* __restrict__ Aim) {
    __shared__ MS s;
    int b = blockIdx.y;
    long off = (long)b * Vv * Cc;
    int row0 = blockIdx.x * 128;
    float acc[2][8][4]; zacc(acc);
    mma_gemm(s, g_gy + off + (long)row0 * Cc, Cc, Are, Cc, 1.0f, acc);
    mma_gemm(s, g_gx + off + (long)row0 * Cc, Cc, Aim, Cc, 1.0f, acc);
    int lane = threadIdx.x & 31, g = lane >> 2, t4 = lane & 3;
    int wid = threadIdx.x >> 5;
    int m0 = (wid & 3) * 32, n0 = (wid >> 2) * 64;
    #pragma unroll
    for (int mt = 0; mt < 2; mt++)
        #pragma unroll
        for (int nt = 0; nt < 8; nt++) {
            int c = n0 + nt * 8 + t4 * 2;
            #pragma unroll
            for (int h = 0; h < 2; h++) {
                int r = row0 + m0 + mt * 16 + g + h * 8;
                long base = off + (long)r * 128 + c;
                float2 gx2 = *(const float2*)(g_gx + base);
                float2 gy2 = *(const float2*)(g_gy + base);
                float2 br2 = *(const float2*)(g_br + base);
                float bi0 = acc[mt][nt][h * 2], bi1 = acc[mt][nt][h * 2 + 1];
                float2 o;
                o.x = tanhf(gx2.x * br2.x + gy2.x * bi0);
                o.y = tanhf(gx2.y * br2.y + gy2.y * bi1);
                *(float2*)(g_gfeat + base) = o;
            }
        }
}

// h0 = relu([x|x_diff|gfeat]@W0 + b0) . grid (128)
__global__ __launch_bounds__(256) void k_mlp0(const float* __restrict__ W0,
                                              const float* __restrict__ b0) {
    __shared__ MS s;
    int row0 = blockIdx.x * 128;
    float acc[2][8][4]; zacc(acc);
    mma_gemm(s, g_x     + (long)row0 * Cc, Cc, W0,             Cc, 1.0f, acc);
    mma_gemm(s, g_xdiff + (long)row0 * Cc, Cc, W0 + 128 * 128, Cc, 1.0f, acc);
    mma_gemm(s, g_gfeat + (long)row0 * Cc, Cc, W0 + 256 * 128, Cc, 1.0f, acc);
    int lane = threadIdx.x & 31, g = lane >> 2, t4 = lane & 3;
    int wid = threadIdx.x >> 5;
    int m0 = (wid & 3) * 32, n0 = (wid >> 2) * 64;
    #pragma unroll
    for (int mt = 0; mt < 2; mt++)
        #pragma unroll
        for (int nt = 0; nt < 8; nt++) {
            int c = n0 + nt * 8 + t4 * 2;
            float2 bb = *(const float2*)(b0 + c);
            int r = row0 + m0 + mt * 16 + g;
            *(float2*)(g_h0 + (long)r * 128 + c) = make_float2(
                fmaxf(acc[mt][nt][0] + bb.x, 0.0f), fmaxf(acc[mt][nt][1] + bb.y, 0.0f));
            *(float2*)(g_h0 + (long)(r + 8) * 128 + c) = make_float2(
                fmaxf(acc[mt][nt][2] + bb.x, 0.0f), fmaxf(acc[mt][nt][3] + bb.y, 0.0f));
        }
}

// h1 = relu(h0@W1 + b1)
__global__ __launch_bounds__(256) void k_mlp1(const float* __restrict__ W1,
                                              const float* __restrict__ b1) {
    __shared__ MS s;
    int row0 = blockIdx.x * 128;
    float acc[2][8][4]; zacc(acc);
    mma_gemm(s, g_h0 + (long)row0 * Cc, Cc, W1, Cc, 1.0f, acc);
    int lane = threadIdx.x & 31, g = lane >> 2, t4 = lane & 3;
    int wid = threadIdx.x >> 5;
    int m0 = (wid & 3) * 32, n0 = (wid >> 2) * 64;
    #pragma unroll
    for (int mt = 0; mt < 2; mt++)
        #pragma unroll
        for (int nt = 0; nt < 8; nt++) {
            int c = n0 + nt * 8 + t4 * 2;
            float2 bb = *(const float2*)(b1 + c);
            int r = row0 + m0 + mt * 16 + g;
            *(float2*)(g_h1 + (long)r * 128 + c) = make_float2(
                fmaxf(acc[mt][nt][0] + bb.x, 0.0f), fmaxf(acc[mt][nt][1] + bb.y, 0.0f));
            *(float2*)(g_h1 + (long)(r + 8) * 128 + c) = make_float2(
                fmaxf(acc[mt][nt][2] + bb.x, 0.0f), fmaxf(acc[mt][nt][3] + bb.y, 0.0f));
        }
}

// x += h1@W2 + b2
__global__ __launch_bounds__(256) void k_mlp2(const float* __restrict__ W2,
                                              const float* __restrict__ b2) {
    __shared__ MS s;
    int row0 = blockIdx.x * 128;
    float acc[2][8][4]; zacc(acc);
    mma_gemm(s, g_h1 + (long)row0 * Cc, Cc, W2, Cc, 1.0f, acc);
    int lane = threadIdx.x & 31, g = lane >> 2, t4 = lane & 3;
    int wid = threadIdx.x >> 5;
    int m0 = (wid & 3) * 32, n0 = (wid >> 2) * 64;
    #pragma unroll
    for (int mt = 0; mt < 2; mt++)
        #pragma unroll
        for (int nt = 0; nt < 8; nt++) {
            int c = n0 + nt * 8 + t4 * 2;
            float2 bb = *(const float2*)(b2 + c);
            #pragma unroll
            for (int h = 0; h < 2; h++) {
                int r = row0 + m0 + mt * 16 + g + h * 8;
                float2 xv = *(const float2*)(g_x + (long)r * 128 + c);
                xv.x += acc[mt][nt][h * 2]     + bb.x;
                xv.y += acc[mt][nt][h * 2 + 1] + bb.y;
                *(float2*)(g_x + (long)r * 128 + c) = xv;
            }
        }
}

// out = x@Wl + bl
__global__ __launch_bounds__(256) void k_final(const float* __restrict__ Wl,
                                               const float* __restrict__ bl,
                                               float* __restrict__ out) {
    __shared__ MS s;
    int row0 = blockIdx.x * 128;
    float acc[2][8][4]; zacc(acc);
    mma_gemm(s, g_x + (long)row0 * Cc, Cc, Wl, Cc, 1.0f, acc);
    int lane = threadIdx.x & 31, g = lane >> 2, t4 = lane & 3;
    int wid = threadIdx.x >> 5;
    int m0 = (wid & 3) * 32, n0 = (wid >> 2) * 64;
    #pragma unroll
    for (int mt = 0; mt < 2; mt++)
        #pragma unroll
        for (int nt = 0; nt < 8; nt++) {
            int c = n0 + nt * 8 + t4 * 2;
            float2 bb = *(const float2*)(bl + c);
            int r = row0 + m0 + mt * 16 + g;
            *(float2*)(out + (long)r * 128 + c) = make_float2(
                acc[mt][nt][0] + bb.x, acc[mt][nt][1] + bb.y);
            *(float2*)(out + (long)(r + 8) * 128 + c) = make_float2(
                acc[mt][nt][2] + bb.x, acc[mt][nt][3] + bb.y);
        }
}

// ---------------- launch ----------------
extern "C" void kernel_launch(void* const* d_in, const int* in_sizes, int n_in,
                              void* d_out, int out_size) {
    const float* x_in  = (const float*)d_in[0];
    const float* mass  = (const float*)d_in[1];
    const float* evals = (const float*)d_in[2];
    const float* evecs = (const float*)d_in[3];
    const float* gradX = (const float*)d_in[4];
    const float* gradY = (const float*)d_in[5];
    const float* Wf    = (const float*)d_in[6];
    const float* bf    = (const float*)d_in[7];
    const float* Wl    = (const float*)d_in[8];
    const float* bl    = (const float*)d_in[9];
    const float* t     = (const float*)d_in[10];
    const float* Are   = (const float*)d_in[11];
    const float* Aim   = (const float*)d_in[12];
    const float* W0    = (const float*)d_in[13];
    const float* b0    = (const float*)d_in[14];
    const float* W1    = (const float*)d_in[15];
    const float* b1    = (const float*)d_in[16];
    const float* W2    = (const float*)d_in[17];
    const float* b2    = (const float*)d_in[18];
    float* out = (float*)d_out;

    k_input<<<(Bb * Vv * Cc) / 256, 256>>>(x_in, Wf, bf);

    // one-time precompute: GXE/GYE via bf16-split tensor cores
    k_bigmm<<<dim3(Vv / 128, Bb, 2), 256>>>(gradX, gradY, evecs);

    for (int i = 0; i < NBLK; i++) {
        k_zero_spec<<<(Bb * Kk * Cc) / 256, 256>>>();
        k_spec<<<dim3(Vv / 128, Bb), 256>>>(evecs, mass);
        k_scale<<<(Bb * Kk * Cc) / 256, 256>>>(evals, t, i);
        k_fbg<<<dim3(Vv / 128, Bb, 3), 256>>>(evecs);
        k_br<<<dim3(Vv / 128, Bb), 256>>>(Are + i * Cc * Cc, Aim + i * Cc * Cc);
        k_gfeat<<<dim3(Vv / 128, Bb), 256>>>(Are + i * Cc * Cc, Aim + i * Cc * Cc);
        k_mlp0<<<(Bb * Vv) / 128, 256>>>(W0 + i * 3 * Cc * Cc, b0 + i * Cc);
        k_mlp1<<<(Bb * Vv) / 128, 256>>>(W1 + i * Cc * Cc, b1 + i * Cc);
        k_mlp2<<<(Bb * Vv) / 128, 256>>>(W2 + i * Cc * Cc, b2 + i * Cc);
    }

    k_final<<<(Bb * Vv) / 128, 256>>>(Wl, bl, out);
}